// round 2
// baseline (speedup 1.0000x reference)
#include <cuda_runtime.h>
#include <cuda_fp16.h>
#include <stdint.h>

// Problem constants
#define NB    16384
#define NL    4
#define NIS   1024
#define NHS   512
#define NOUT  3
#define NM    (NB*NL)        // 65536 rows
#define MTILE 128
#define NTILE 256            // N columns per CTA (NHS split in 2)
#define KCH   64             // K columns per chunk
#define NCH   (NIS/KCH)      // 16
#define NTHR  512            // 16 warps: 4 (m) x 4 (n)

// Pre-split, pre-swizzled W1 tiles: [variant hi/lo][chunk][n-half][64 k x 256 n]
__device__ __align__(16) __half g_W[2][NCH][2][KCH * NTILE];
// Per-half partial outputs (deterministic 2-way combine)
__device__ float g_part[2][NM][NOUT];

// ---------------- helpers ----------------
static __device__ __forceinline__ uint32_t smem_u32(const void* p) {
    uint32_t a;
    asm("{ .reg .u64 t; cvta.to.shared.u64 t, %1; cvt.u32.u64 %0, t; }"
        : "=r"(a) : "l"(p));
    return a;
}

#define LDSM_X4(r, addr)                                                      \
    asm volatile("ldmatrix.sync.aligned.m8n8.x4.shared.b16 "                  \
                 "{%0,%1,%2,%3}, [%4];"                                       \
                 : "=r"((r)[0]), "=r"((r)[1]), "=r"((r)[2]), "=r"((r)[3])     \
                 : "r"(addr))

#define LDSM_X4_T(r, addr)                                                    \
    asm volatile("ldmatrix.sync.aligned.m8n8.x4.trans.shared.b16 "            \
                 "{%0,%1,%2,%3}, [%4];"                                       \
                 : "=r"((r)[0]), "=r"((r)[1]), "=r"((r)[2]), "=r"((r)[3])     \
                 : "r"(addr))

static __device__ __forceinline__ void mma16816(float* c, const uint32_t* a,
                                                const uint32_t* b) {
    asm volatile(
        "mma.sync.aligned.m16n8k16.row.col.f32.f16.f16.f32 "
        "{%0,%1,%2,%3}, {%4,%5,%6,%7}, {%8,%9}, {%0,%1,%2,%3};"
        : "+f"(c[0]), "+f"(c[1]), "+f"(c[2]), "+f"(c[3])
        : "r"(a[0]), "r"(a[1]), "r"(a[2]), "r"(a[3]), "r"(b[0]), "r"(b[1]));
}

// ---------------- prep: split W1 -> fp16 hi/lo, swizzled tile layout ----------------
__global__ void prep_w_kernel(const float* __restrict__ W1) {
    int e = blockIdx.x * blockDim.x + threadIdx.x;
    if (e >= NIS * NHS) return;
    int k_g = e >> 9;          // 0..1023 (IS index)
    int n_g = e & 511;         // 0..511  (HS index), coalesced read
    float w = W1[e];
    __half hi = __float2half_rn(w);
    __half lo = __float2half_rn(w - __half2float(hi));
    int ch = k_g >> 6, k = k_g & 63;
    int nh = n_g >> 8, n = n_g & 255;
    // swizzled element index within [64][256] tile: 512B rows, 16B-chunk xor swizzle
    int idx = k * 256 + ((((n >> 3) ^ (k & 7)) << 3) | (n & 7));
    g_W[0][ch][nh][idx] = hi;
    g_W[1][ch][nh][idx] = lo;
}

// ---------------- main fused kernel ----------------
// SMEM map (dynamic):
//   [0,      16384)  A_hi  128x64 fp16, 128B rows, xor-swizzled 16B chunks
//   [16384,  32768)  A_lo
//   [32768,  65536)  B_hi  64x256 fp16, 512B rows, xor-swizzled
//   [65536,  98304)  B_lo
//   [98304, 122880)  red   [128][16][3] fp32
//   [122880,123392)  meta  [128] int
#define SMEM_BYTES 123392

__global__ void __launch_bounds__(NTHR, 1)
wop_main_kernel(const float* __restrict__ wenc,
                const float* __restrict__ repeat_t,
                const float* __restrict__ b1,
                const float* __restrict__ W2,
                const int*   __restrict__ wn,
                const int*   __restrict__ wc)
{
    extern __shared__ char smem[];
    float* red  = (float*)(smem + 98304);
    int*   meta = (int*)(smem + 122880);

    const int tid  = threadIdx.x;
    const int lane = tid & 31;
    const int wid  = tid >> 5;
    const int wm   = wid & 3;    // m quadrant: rows wm*32 .. +31
    const int wq   = wid >> 2;   // n quadrant: cols wq*64 .. +63

    const int bx   = blockIdx.x;
    const int m0   = (bx >> 1) * MTILE;
    const int nh   = bx & 1;     // which 256-col half of HS

    // row metadata: -2 invalid, -1 valid no-add, r>=1 -> add repeat[r]
    if (tid < MTILE) {
        int m = m0 + tid;
        int b = m >> 2, l = m & 3;
        int code;
        if (l >= wn[b]) {
            code = -2;
        } else {
            int wcl = wc[b * 4 + l];
            int r = 0;
            for (int j = 0; j < l; j++) r += (wc[b * 4 + j] == wcl);
            code = (r > 0) ? r : -1;
        }
        meta[tid] = code;
    }

    const uint32_t sb = smem_u32(smem);

    // ldmatrix address precompute
    // A: frag matrices -> lane l: m = mbase + ((l>>3)&1)*8 + (l&7), kchunk-half = l>>4
    uint32_t a_mbase[2], a_msw[2];
    {
        int mrow0 = wm * 32 + ((lane >> 3) & 1) * 8 + (lane & 7);
        a_mbase[0] = (uint32_t)(mrow0) * 128u;
        a_mbase[1] = (uint32_t)(mrow0 + 16) * 128u;
        a_msw[0] = (uint32_t)(mrow0 & 7);
        a_msw[1] = (uint32_t)((mrow0 + 16) & 7);
    }
    const uint32_t a_hi_lane = (uint32_t)(lane >> 4);  // 0/1 -> k half
    // B: lane l: k = s*16 + klocal, n = wq*64 + np*16 + (l>>4)*8
    const int klocal = ((lane >> 3) & 1) * 8 + (lane & 7);
    const uint32_t b_kbase = (uint32_t)klocal * 512u;
    const uint32_t b_ksw   = (uint32_t)(klocal & 7);
    const uint32_t b_nidx0 = (uint32_t)(wq * 8 + (lane >> 4));

    float acc[2][8][4];
    #pragma unroll
    for (int i = 0; i < 2; i++)
        #pragma unroll
        for (int j = 0; j < 8; j++)
            #pragma unroll
            for (int q = 0; q < 4; q++) acc[i][j][q] = 0.f;

    for (int ch = 0; ch < NCH; ch++) {
        __syncthreads();  // previous compute done reading SMEM (and meta visible on ch==0)

        // ---- build A_hi / A_lo ----
        #pragma unroll
        for (int it = 0; it < 2; it++) {
            int u   = tid + it * NTHR;     // 0..1023 = 128 rows x 8 kgroups
            int row = u >> 3;
            int kg  = u & 7;
            int code = meta[row];
            float4 v0 = make_float4(0.f, 0.f, 0.f, 0.f);
            float4 v1 = v0;
            if (code != -2) {
                const float* p = wenc + (size_t)(m0 + row) * NIS + ch * KCH + kg * 8;
                v0 = *(const float4*)p;
                v1 = *(const float4*)(p + 4);
                if (code >= 1) {
                    const float* q = repeat_t + (size_t)code * NIS + ch * KCH + kg * 8;
                    float4 r0 = *(const float4*)q;
                    float4 r1 = *(const float4*)(q + 4);
                    v0.x += r0.x; v0.y += r0.y; v0.z += r0.z; v0.w += r0.w;
                    v1.x += r1.x; v1.y += r1.y; v1.z += r1.z; v1.w += r1.w;
                }
            }
            __half2 h0 = __floats2half2_rn(v0.x, v0.y);
            __half2 h1 = __floats2half2_rn(v0.z, v0.w);
            __half2 h2 = __floats2half2_rn(v1.x, v1.y);
            __half2 h3 = __floats2half2_rn(v1.z, v1.w);
            float2 f0 = __half22float2(h0), f1 = __half22float2(h1);
            float2 f2 = __half22float2(h2), f3 = __half22float2(h3);
            __half2 l0 = __floats2half2_rn(v0.x - f0.x, v0.y - f0.y);
            __half2 l1 = __floats2half2_rn(v0.z - f1.x, v0.w - f1.y);
            __half2 l2 = __floats2half2_rn(v1.x - f2.x, v1.y - f2.y);
            __half2 l3 = __floats2half2_rn(v1.z - f3.x, v1.w - f3.y);
            uint32_t soff = (uint32_t)row * 128u + (uint32_t)((kg ^ (row & 7)) << 4);
            uint4 hv, lv;
            hv.x = *(uint32_t*)&h0; hv.y = *(uint32_t*)&h1;
            hv.z = *(uint32_t*)&h2; hv.w = *(uint32_t*)&h3;
            lv.x = *(uint32_t*)&l0; lv.y = *(uint32_t*)&l1;
            lv.z = *(uint32_t*)&l2; lv.w = *(uint32_t*)&l3;
            *(uint4*)(smem + soff)         = hv;
            *(uint4*)(smem + 16384 + soff) = lv;
        }

        // ---- copy B tiles (pre-split + pre-swizzled), 32KB each ----
        {
            const uint4* srcH = (const uint4*)&g_W[0][ch][nh][0];
            const uint4* srcL = (const uint4*)&g_W[1][ch][nh][0];
            uint4* dH = (uint4*)(smem + 32768);
            uint4* dL = (uint4*)(smem + 65536);
            #pragma unroll
            for (int i = 0; i < 4; i++) {
                int idx = tid + i * NTHR;
                dH[idx] = srcH[idx];
                dL[idx] = srcL[idx];
            }
        }
        __syncthreads();

        // ---- compute: 4 k16-steps ----
        #pragma unroll
        for (int s = 0; s < 4; s++) {
            uint32_t ah[2][4], al[2][4];
            #pragma unroll
            for (int mt = 0; mt < 2; mt++) {
                uint32_t ci  = (uint32_t)(2 * s) + a_hi_lane;
                uint32_t off = a_mbase[mt] + (((ci ^ a_msw[mt])) << 4);
                LDSM_X4(ah[mt], sb + off);
                LDSM_X4(al[mt], sb + 16384u + off);
            }
            #pragma unroll
            for (int np = 0; np < 4; np++) {
                uint32_t offB = (uint32_t)(s * 8192) + b_kbase +
                                (((b_nidx0 + (uint32_t)(2 * np)) ^ b_ksw) << 4);
                uint32_t bh[4], bl[4];
                LDSM_X4_T(bh, sb + 32768u + offB);
                LDSM_X4_T(bl, sb + 65536u + offB);
                #pragma unroll
                for (int mt = 0; mt < 2; mt++) {
                    #pragma unroll
                    for (int nn = 0; nn < 2; nn++) {
                        float* c = acc[mt][np * 2 + nn];
                        mma16816(c, ah[mt], bh + 2 * nn);
                        mma16816(c, ah[mt], bl + 2 * nn);
                        mma16816(c, al[mt], bh + 2 * nn);
                    }
                }
            }
        }
    }

    // ---- epilogue: +b1, tanh, partial x W2 ----
    __syncthreads();  // done with A/B SMEM; red region free
    const int slot = wq * 4 + (lane & 3);
    #pragma unroll
    for (int mt = 0; mt < 2; mt++) {
        #pragma unroll
        for (int rh = 0; rh < 2; rh++) {
            float s0 = 0.f, s1 = 0.f, s2 = 0.f;
            #pragma unroll
            for (int nt = 0; nt < 8; nt++) {
                int col_g = nh * NTILE + wq * 64 + nt * 8 + (lane & 3) * 2;
                #pragma unroll
                for (int cc = 0; cc < 2; cc++) {
                    float h = tanhf(acc[mt][nt][rh * 2 + cc] + b1[col_g + cc]);
                    s0 = fmaf(h, W2[(col_g + cc) * 3 + 0], s0);
                    s1 = fmaf(h, W2[(col_g + cc) * 3 + 1], s1);
                    s2 = fmaf(h, W2[(col_g + cc) * 3 + 2], s2);
                }
            }
            int row = wm * 32 + mt * 16 + (lane >> 2) + rh * 8;
            float* rp = red + (size_t)row * 48 + slot * 3;
            rp[0] = s0; rp[1] = s1; rp[2] = s2;
        }
    }
    __syncthreads();
    if (tid < MTILE) {
        float s0 = 0.f, s1 = 0.f, s2 = 0.f;
        const float* rp = red + (size_t)tid * 48;
        #pragma unroll
        for (int s = 0; s < 16; s++) {
            s0 += rp[s * 3 + 0];
            s1 += rp[s * 3 + 1];
            s2 += rp[s * 3 + 2];
        }
        g_part[nh][m0 + tid][0] = s0;
        g_part[nh][m0 + tid][1] = s1;
        g_part[nh][m0 + tid][2] = s2;
    }
}

// ---------------- combine: out = part0 + part1 + b2 ----------------
__global__ void combine_kernel(const float* __restrict__ b2, float* __restrict__ out) {
    int m = blockIdx.x * blockDim.x + threadIdx.x;
    if (m >= NM) return;
    float b0 = b2[0], bb1 = b2[1], bb2 = b2[2];
    out[(size_t)m * 3 + 0] = g_part[0][m][0] + g_part[1][m][0] + b0;
    out[(size_t)m * 3 + 1] = g_part[0][m][1] + g_part[1][m][1] + bb1;
    out[(size_t)m * 3 + 2] = g_part[0][m][2] + g_part[1][m][2] + bb2;
}

// ---------------- launch ----------------
extern "C" void kernel_launch(void* const* d_in, const int* in_sizes, int n_in,
                              void* d_out, int out_size) {
    const float* wenc   = (const float*)d_in[0];
    const float* repeat = (const float*)d_in[1];
    const float* W1     = (const float*)d_in[2];
    const float* b1     = (const float*)d_in[3];
    const float* W2     = (const float*)d_in[4];
    const float* b2     = (const float*)d_in[5];
    const int*   wn     = (const int*)d_in[6];
    const int*   wc     = (const int*)d_in[7];
    float* out = (float*)d_out;
    (void)in_sizes; (void)n_in; (void)out_size;

    prep_w_kernel<<<(NIS * NHS + 255) / 256, 256>>>(W1);

    cudaFuncSetAttribute(wop_main_kernel,
                         cudaFuncAttributeMaxDynamicSharedMemorySize, SMEM_BYTES);
    wop_main_kernel<<<(NM / MTILE) * 2, NTHR, SMEM_BYTES>>>(
        wenc, repeat, b1, W2, wn, wc);

    combine_kernel<<<(NM + 255) / 256, 256>>>(b2, out);
}